// round 7
// baseline (speedup 1.0000x reference)
#include <cuda_runtime.h>
#include <cuda_bf16.h>
#include <math.h>
#include <stdint.h>

#define B_ 8192
#define D_ 4096
#define E_ 512
#define MARGIN 3.0f

// ---------------- scratch (device globals; no cudaMalloc allowed) ----------
__device__ __align__(16) __nv_bfloat16 g_Xb[(size_t)B_ * D_];   // 64MB
__device__ __align__(16) __nv_bfloat16 g_Cb[(size_t)E_ * D_];   // 4MB
__device__ __align__(16) float g_dist[(size_t)B_ * E_];         // 16MB approx distances
__device__ float  g_norm[E_];      // exact fp32 ||e||^2
__device__ float  g_xnorm[B_];     // exact fp32 ||x||^2
__device__ float  g_rowdist[B_];   // chosen ||e||^2 - 2*dot  (approx or exact)
__device__ int    g_idx[B_];
__device__ int    g_ncand[B_];
__device__ int    g_cand[B_][8];
__device__ int    g_hist[E_];

// ---------------- PTX helpers ----------------------------------------------
__device__ __forceinline__ uint32_t smem_u32(const void* p) {
    uint32_t a;
    asm("{ .reg .u64 t; cvta.to.shared.u64 t, %1; cvt.u32.u64 %0, t; }" : "=r"(a) : "l"(p));
    return a;
}
__device__ __forceinline__ void cp16(uint32_t dst, const void* src) {
    asm volatile("cp.async.cg.shared.global [%0], [%1], 16;" :: "r"(dst), "l"(src) : "memory");
}
__device__ __forceinline__ void ldmx4(uint32_t* f, uint32_t addr) {
    asm volatile("ldmatrix.sync.aligned.m8n8.x4.shared.b16 {%0,%1,%2,%3}, [%4];"
                 : "=r"(f[0]), "=r"(f[1]), "=r"(f[2]), "=r"(f[3]) : "r"(addr));
}
__device__ __forceinline__ void mma16816(float* c, const uint32_t* a,
                                         uint32_t b0, uint32_t b1) {
    asm volatile(
        "mma.sync.aligned.m16n8k16.row.col.f32.bf16.bf16.f32 "
        "{%0,%1,%2,%3}, {%4,%5,%6,%7}, {%8,%9}, {%0,%1,%2,%3};"
        : "+f"(c[0]), "+f"(c[1]), "+f"(c[2]), "+f"(c[3])
        : "r"(a[0]), "r"(a[1]), "r"(a[2]), "r"(a[3]), "r"(b0), "r"(b1));
}

// ---------------- small kernels ---------------------------------------------
__global__ void k_init() {
    int i = blockIdx.x * 256 + threadIdx.x;
    if (i < E_) g_hist[i] = 0;
    for (int r = i; r < B_; r += gridDim.x * 256) g_ncand[r] = 0;
}

// fp32 -> bf16 conversion of X + per-row ||x||^2. One block (512 thr) per row.
__global__ __launch_bounds__(512) void k_convX(const float* __restrict__ X) {
    int row = blockIdx.x;
    int t = threadIdx.x;
    const float4* x4 = reinterpret_cast<const float4*>(X) + (size_t)row * 1024;
    float4 a = x4[2 * t], b = x4[2 * t + 1];
    __nv_bfloat162 p0 = __float22bfloat162_rn(make_float2(a.x, a.y));
    __nv_bfloat162 p1 = __float22bfloat162_rn(make_float2(a.z, a.w));
    __nv_bfloat162 p2 = __float22bfloat162_rn(make_float2(b.x, b.y));
    __nv_bfloat162 p3 = __float22bfloat162_rn(make_float2(b.z, b.w));
    uint4 v;
    v.x = ((uint32_t)__bfloat16_as_ushort(p0.y) << 16) | __bfloat16_as_ushort(p0.x);
    v.y = ((uint32_t)__bfloat16_as_ushort(p1.y) << 16) | __bfloat16_as_ushort(p1.x);
    v.z = ((uint32_t)__bfloat16_as_ushort(p2.y) << 16) | __bfloat16_as_ushort(p2.x);
    v.w = ((uint32_t)__bfloat16_as_ushort(p3.y) << 16) | __bfloat16_as_ushort(p3.x);
    reinterpret_cast<uint4*>(g_Xb)[(size_t)row * 512 + t] = v;

    float s = a.x * a.x + a.y * a.y + a.z * a.z + a.w * a.w
            + b.x * b.x + b.y * b.y + b.z * b.z + b.w * b.w;
    __shared__ float sh[512];
    sh[t] = s;
    __syncthreads();
    for (int st = 256; st > 0; st >>= 1) {
        if (t < st) sh[t] += sh[t + st];
        __syncthreads();
    }
    if (t == 0) g_xnorm[row] = sh[0];
}

// codebook: exact fp32 norms + bf16 copy
__global__ __launch_bounds__(256) void k_normsC(const float* __restrict__ cb) {
    int e = blockIdx.x;
    const float* row = cb + (size_t)e * D_;
    __nv_bfloat16* brow = g_Cb + (size_t)e * D_;
    float s = 0.f;
    for (int d = threadIdx.x; d < D_; d += 256) {
        float v = row[d];
        s += v * v;
        brow[d] = __float2bfloat16_rn(v);
    }
    __shared__ float sh[256];
    sh[threadIdx.x] = s;
    __syncthreads();
    for (int st = 128; st > 0; st >>= 1) {
        if (threadIdx.x < st) sh[threadIdx.x] += sh[threadIdx.x + st];
        __syncthreads();
    }
    if (threadIdx.x == 0) g_norm[e] = sh[0];
}

// ---------------- mma.sync bf16 GEMM ----------------------------------------
// CTA tile 128x128, BK=32, 4-stage cp.async pipeline, 8 warps (2x4), each 64x32.
// SMEM: stage s at s*16KB: [A 128x32bf16 8KB][B 128x32bf16 8KB]; cns fp32[128]
// at 64KB. Total 66048. Swizzle: row r (64B), 16B-unit u: u' = u ^ ((r>>1)&3).
#define BK 32
#define SMEM_GEMM (4 * 16384 + 512)

__device__ __forceinline__ void load_tile(uint32_t as, int tid,
                                          const __nv_bfloat16* __restrict__ gA,
                                          const __nv_bfloat16* __restrict__ gB,
                                          int kk) {
    uint32_t bs = as + 8192;
#pragma unroll
    for (int i = 0; i < 2; i++) {
        int id = tid + 256 * i;
        int r = id >> 2, u = id & 3;
        uint32_t off = (uint32_t)(r * 64 + ((u ^ ((r >> 1) & 3)) << 4));
        cp16(as + off, gA + (size_t)r * D_ + kk + u * 8);
        cp16(bs + off, gB + (size_t)r * D_ + kk + u * 8);
    }
}

__global__ __launch_bounds__(256, 2) void k_gemm_mma() {
    extern __shared__ char smem[];
    uint32_t sb = smem_u32(smem);
    float* cns = (float*)(smem + 65536);
    int tid = threadIdx.x, wid = tid >> 5, lane = tid & 31;
    int n0 = blockIdx.x * 128, m0 = blockIdx.y * 128;
    int wm = (wid >> 2) * 64, wn = (wid & 3) * 32;

    const __nv_bfloat16* gA = g_Xb + (size_t)m0 * D_;
    const __nv_bfloat16* gB = g_Cb + (size_t)n0 * D_;
    for (int i = tid; i < 128; i += 256) cns[i] = g_norm[n0 + i];

    // precomputed ldmatrix row offsets (row*64 part; u varies per ks)
    int arow[4], brow[2];
#pragma unroll
    for (int mi = 0; mi < 4; mi++)
        arow[mi] = wm + 16 * mi + (lane & 7) + 8 * ((lane >> 3) & 1);
#pragma unroll
    for (int p = 0; p < 2; p++)
        brow[p] = wn + 16 * p + (lane & 7) + 8 * ((lane >> 4) & 1);
    int au = (lane >> 4) & 1, bu = (lane >> 3) & 1;

    float acc[4][4][4];
#pragma unroll
    for (int a = 0; a < 4; a++)
#pragma unroll
        for (int b = 0; b < 4; b++)
#pragma unroll
            for (int c = 0; c < 4; c++) acc[a][b][c] = 0.f;

    // prologue: stages 0,1,2
    load_tile(sb, tid, gA, gB, 0);
    asm volatile("cp.async.commit_group;" ::: "memory");
    load_tile(sb + 16384, tid, gA, gB, BK);
    asm volatile("cp.async.commit_group;" ::: "memory");
    load_tile(sb + 2 * 16384, tid, gA, gB, 2 * BK);
    asm volatile("cp.async.commit_group;" ::: "memory");

    const int NKT = D_ / BK;   // 128
    for (int kt = 0; kt < NKT; kt++) {
        asm volatile("cp.async.wait_group 2;" ::: "memory");
        __syncthreads();
        if (kt + 3 < NKT)
            load_tile(sb + ((kt + 3) & 3) * 16384, tid, gA, gB, (kt + 3) * BK);
        asm volatile("cp.async.commit_group;" ::: "memory");

        uint32_t as = sb + (kt & 3) * 16384;
        uint32_t bs = as + 8192;

#pragma unroll
        for (int ks = 0; ks < 2; ks++) {
            uint32_t af[4][4], bf[2][4];
#pragma unroll
            for (int mi = 0; mi < 4; mi++) {
                int r = arow[mi], u = ks * 2 + au;
                ldmx4(af[mi], as + r * 64 + ((u ^ ((r >> 1) & 3)) << 4));
            }
#pragma unroll
            for (int p = 0; p < 2; p++) {
                int r = brow[p], u = ks * 2 + bu;
                ldmx4(bf[p], bs + r * 64 + ((u ^ ((r >> 1) & 3)) << 4));
            }
#pragma unroll
            for (int mi = 0; mi < 4; mi++)
#pragma unroll
                for (int p = 0; p < 2; p++) {
                    mma16816(acc[mi][2 * p],     af[mi], bf[p][0], bf[p][1]);
                    mma16816(acc[mi][2 * p + 1], af[mi], bf[p][2], bf[p][3]);
                }
        }
    }

    // epilogue: approx distance = ||c||^2 - 2*dot  -> g_dist
    int gid = lane >> 2, tig = lane & 3;
#pragma unroll
    for (int mi = 0; mi < 4; mi++) {
        int row = m0 + wm + 16 * mi + gid;
#pragma unroll
        for (int nj = 0; nj < 4; nj++) {
            int c = wn + 8 * nj + 2 * tig;
            float cn0 = cns[c], cn1 = cns[c + 1];
            float2 v0 = make_float2(cn0 - 2.f * acc[mi][nj][0], cn1 - 2.f * acc[mi][nj][1]);
            float2 v1 = make_float2(cn0 - 2.f * acc[mi][nj][2], cn1 - 2.f * acc[mi][nj][3]);
            *reinterpret_cast<float2*>(g_dist + (size_t)row * E_ + n0 + c) = v0;
            *reinterpret_cast<float2*>(g_dist + (size_t)(row + 8) * E_ + n0 + c) = v1;
        }
    }
}

// ---------------- argmin + candidate collection (warp per row) ---------------
__global__ __launch_bounds__(256) void k_argmin() {
    int row = (blockIdx.x * 256 + threadIdx.x) >> 5;
    int lane = threadIdx.x & 31;
    if (row >= B_) return;
    const float4* dp = reinterpret_cast<const float4*>(g_dist + (size_t)row * E_);
    float4 v[4];
    float best = INFINITY;
    int bidx = 1 << 30;
#pragma unroll
    for (int j = 0; j < 4; j++) {
        v[j] = dp[lane + 32 * j];
        int c0 = (lane + 32 * j) * 4;
        const float* f = reinterpret_cast<const float*>(&v[j]);
#pragma unroll
        for (int e = 0; e < 4; e++) {
            float d = f[e];
            int c = c0 + e;
            if (d < best || (d == best && c < bidx)) { best = d; bidx = c; }
        }
    }
#pragma unroll
    for (int off = 16; off > 0; off >>= 1) {
        float ov = __shfl_xor_sync(0xffffffffu, best, off);
        int   oi = __shfl_xor_sync(0xffffffffu, bidx, off);
        if (ov < best || (ov == best && oi < bidx)) { best = ov; bidx = oi; }
    }
    float thr = best + MARGIN;
#pragma unroll
    for (int j = 0; j < 4; j++) {
        int c0 = (lane + 32 * j) * 4;
        const float* f = reinterpret_cast<const float*>(&v[j]);
#pragma unroll
        for (int e = 0; e < 4; e++) {
            if (f[e] <= thr) {
                int p = atomicAdd(&g_ncand[row], 1);
                if (p < 8) g_cand[row][p] = c0 + e;
            }
        }
    }
    if (lane == 0) { g_idx[row] = bidx; g_rowdist[row] = best; }
}

// ---------------- exact fp32 rescore of ambiguous rows -----------------------
__global__ __launch_bounds__(128) void k_rescore(const float* __restrict__ X,
                                                 const float* __restrict__ Cb) {
    int b = blockIdx.x;
    int n = g_ncand[b];
    if (n <= 1) return;                     // unambiguous: bf16 winner stands
    __shared__ float sh[128];
    const float4* x4 = reinterpret_cast<const float4*>(X + (size_t)b * D_);
    int total = (n <= 8) ? n : E_;          // >8 candidates: full exact scan
    float bestd = INFINITY;
    int besti = 1 << 30;
    for (int c = 0; c < total; c++) {
        int e = (n <= 8) ? g_cand[b][c] : c;
        const float4* c4 = reinterpret_cast<const float4*>(Cb + (size_t)e * D_);
        float s = 0.f;
        for (int i = threadIdx.x; i < D_ / 4; i += 128) {
            float4 xv = x4[i], cv = c4[i];
            s += xv.x * cv.x + xv.y * cv.y + xv.z * cv.z + xv.w * cv.w;
        }
        sh[threadIdx.x] = s;
        __syncthreads();
        for (int st = 64; st > 0; st >>= 1) {
            if (threadIdx.x < st) sh[threadIdx.x] += sh[threadIdx.x + st];
            __syncthreads();
        }
        float d = g_norm[e] - 2.f * sh[0];
        if (d < bestd || (d == bestd && e < besti)) { bestd = d; besti = e; }
        __syncthreads();
    }
    if (threadIdx.x == 0) { g_idx[b] = besti; g_rowdist[b] = bestd; }
}

// ---------------- outputs (no X read; quantized_st == codebook row) ----------
__global__ __launch_bounds__(512) void k_out(const float* __restrict__ Cb,
                                             float* __restrict__ outQ,
                                             float* __restrict__ outEnc) {
    __shared__ float qs[D_];
    int b = blockIdx.x;
    int t = threadIdx.x;
    int idx = g_idx[b];

    if (t == 0) atomicAdd(&g_hist[idx], 1);

    // one-hot encodings: 512 floats per row = 256 float2 stores (t < 256 only!)
    if (t < 256) {
        float2 e2;
        int c = 2 * t;
        e2.x = (c == idx) ? 1.f : 0.f;
        e2.y = (c + 1 == idx) ? 1.f : 0.f;
        reinterpret_cast<float2*>(outEnc + (size_t)b * E_)[t] = e2;
    }

    // stage codebook row in smem (aligned float4 reads)
    const float4* c4 = reinterpret_cast<const float4*>(Cb + (size_t)idx * D_);
    float4* q4 = reinterpret_cast<float4*>(qs);
#pragma unroll
    for (int i = 0; i < 2; i++) q4[t + 512 * i] = c4[t + 512 * i];
    __syncthreads();

    // outQ row is 4B-aligned only (global offset 1 + b*4096).
    // j=0..2 and j=4095 scalar; j in [3,4095) as 1023 aligned float4 stores.
    float* o = outQ + (size_t)b * D_;
    if (t < 3) o[t] = qs[t];
    if (t == 3) o[4095] = qs[4095];
    for (int i = t; i < 1023; i += 512) {
        int j = 3 + 4 * i;
        float4 v = make_float4(qs[j], qs[j + 1], qs[j + 2], qs[j + 3]);
        *reinterpret_cast<float4*>(o + j) = v;
    }
}

// ---------------- finalize: loss from row distances + perplexity -------------
__global__ __launch_bounds__(512) void k_final(float* __restrict__ out) {
    __shared__ double sh[512];
    int t = threadIdx.x;

    // loss = 1.25 * sum_rows(||x||^2 + rowdist) / (B*D)
    double s = 0.0;
    for (int i = t; i < B_; i += 512)
        s += (double)(g_xnorm[i] + g_rowdist[i]);
    sh[t] = s;
    __syncthreads();
    for (int st = 256; st > 0; st >>= 1) {
        if (t < st) sh[t] += sh[t + st];
        __syncthreads();
    }
    double lsum = sh[0];
    __syncthreads();

    double p = (double)g_hist[t] / (double)B_;
    sh[t] = p * log(p + 1e-10);
    __syncthreads();
    for (int st = 256; st > 0; st >>= 1) {
        if (t < st) sh[t] += sh[t + st];
        __syncthreads();
    }
    if (t == 0) {
        double mse = lsum / ((double)B_ * (double)D_);
        out[0] = (float)(1.25 * mse);
        out[1 + (size_t)B_ * D_] = (float)exp(-sh[0]);
    }
}

// ---------------------------------------------------------------------------
extern "C" void kernel_launch(void* const* d_in, const int* in_sizes, int n_in,
                              void* d_out, int out_size) {
    (void)in_sizes; (void)n_in; (void)out_size;
    const float* X  = (const float*)d_in[0];
    const float* Cb = (const float*)d_in[1];
    float* out = (float*)d_out;

    float* outQ   = out + 1;
    float* outEnc = out + 2 + (size_t)B_ * D_;

    cudaFuncSetAttribute(k_gemm_mma, cudaFuncAttributeMaxDynamicSharedMemorySize,
                         SMEM_GEMM);

    k_init<<<32, 256>>>();
    k_convX<<<B_, 512>>>(X);
    k_normsC<<<E_, 256>>>(Cb);
    dim3 gg(E_ / 128, B_ / 128);
    k_gemm_mma<<<gg, 256, SMEM_GEMM>>>();
    k_argmin<<<B_ / 8, 256>>>();
    k_rescore<<<B_, 128>>>(X, Cb);
    k_out<<<B_, 512>>>(Cb, outQ, outEnc);
    k_final<<<1, 512>>>(out);
}

// round 9
// speedup vs baseline: 1.0732x; 1.0732x over previous
#include <cuda_runtime.h>
#include <cuda_bf16.h>
#include <math.h>
#include <stdint.h>

#define B_ 8192
#define D_ 4096
#define E_ 512
#define MARGIN 3.0f

// ---------------- scratch (device globals; no cudaMalloc allowed) ----------
__device__ __align__(16) __nv_bfloat16 g_Cb[(size_t)E_ * D_];   // 4MB
__device__ __align__(16) float g_dist[(size_t)B_ * E_];         // 16MB approx distances
__device__ float  g_norm[E_];      // exact fp32 ||e||^2
__device__ float  g_rowdist[B_];   // chosen ||e||^2 - 2*dot  (approx or exact)
__device__ double g_xsum;          // sum over all x^2 (exact-ish fp32->double)
__device__ int    g_idx[B_];
__device__ int    g_ncand[B_];
__device__ int    g_cand[B_][8];
__device__ int    g_hist[E_];

// ---------------- PTX helpers ----------------------------------------------
__device__ __forceinline__ uint32_t smem_u32(const void* p) {
    uint32_t a;
    asm("{ .reg .u64 t; cvta.to.shared.u64 t, %1; cvt.u32.u64 %0, t; }" : "=r"(a) : "l"(p));
    return a;
}
__device__ __forceinline__ void cp16(uint32_t dst, const void* src) {
    asm volatile("cp.async.cg.shared.global [%0], [%1], 16;" :: "r"(dst), "l"(src) : "memory");
}
__device__ __forceinline__ void ldmx4(uint32_t* f, uint32_t addr) {
    asm volatile("ldmatrix.sync.aligned.m8n8.x4.shared.b16 {%0,%1,%2,%3}, [%4];"
                 : "=r"(f[0]), "=r"(f[1]), "=r"(f[2]), "=r"(f[3]) : "r"(addr));
}
__device__ __forceinline__ void mma16816(float* c, const uint32_t* a,
                                         uint32_t b0, uint32_t b1) {
    asm volatile(
        "mma.sync.aligned.m16n8k16.row.col.f32.bf16.bf16.f32 "
        "{%0,%1,%2,%3}, {%4,%5,%6,%7}, {%8,%9}, {%0,%1,%2,%3};"
        : "+f"(c[0]), "+f"(c[1]), "+f"(c[2]), "+f"(c[3])
        : "r"(a[0]), "r"(a[1]), "r"(a[2]), "r"(a[3]), "r"(b0), "r"(b1));
}
__device__ __forceinline__ uint32_t pack_bf2(float lo, float hi) {
    __nv_bfloat162 p = __float22bfloat162_rn(make_float2(lo, hi));
    return ((uint32_t)__bfloat16_as_ushort(p.y) << 16) | __bfloat16_as_ushort(p.x);
}

// ---------------- small kernels ---------------------------------------------
__global__ void k_init() {
    int i = blockIdx.x * 256 + threadIdx.x;
    if (i < E_) g_hist[i] = 0;
    for (int r = i; r < B_; r += gridDim.x * 256) g_ncand[r] = 0;
    if (blockIdx.x == 0 && threadIdx.x == 0) g_xsum = 0.0;
}

// codebook: exact fp32 norms + bf16 copy
__global__ __launch_bounds__(256) void k_normsC(const float* __restrict__ cb) {
    int e = blockIdx.x;
    const float* row = cb + (size_t)e * D_;
    __nv_bfloat16* brow = g_Cb + (size_t)e * D_;
    float s = 0.f;
    for (int d = threadIdx.x; d < D_; d += 256) {
        float v = row[d];
        s += v * v;
        brow[d] = __float2bfloat16_rn(v);
    }
    __shared__ float sh[256];
    sh[threadIdx.x] = s;
    __syncthreads();
    for (int st = 128; st > 0; st >>= 1) {
        if (threadIdx.x < st) sh[threadIdx.x] += sh[threadIdx.x + st];
        __syncthreads();
    }
    if (threadIdx.x == 0) g_norm[e] = sh[0];
}

// ---------------- mma.sync bf16 GEMM (A = fp32 X, converted in-kernel) ------
// CTA tile 128x128, BK=64, 8 warps (2x4) each 64x32.
// A: fp32 ldg.128 prefetch (1 tile ahead) -> cvt -> STS bf16, 2 stages.
// B: cp.async bf16 from g_Cb, 3 stages.
// SMEM: A0=0, A1=16K, B0=32K, B1=48K, B2=64K (each 16KB, 128 rows x 128B,
// swizzle: unit u (16B) at row r -> u ^ (r&7)); cns fp32[128] at 80K.
#define BK 64
#define SOFF_A0 0
#define SOFF_A1 16384
#define SOFF_B0 32768
#define SOFF_CN 81920
#define SMEM_GEMM 82432

__global__ __launch_bounds__(256, 2) void k_gemm_mma(const float* __restrict__ X) {
    extern __shared__ char smem[];
    uint32_t sb = smem_u32(smem);
    float* cns = (float*)(smem + SOFF_CN);
    int tid = threadIdx.x, wid = tid >> 5, lane = tid & 31;
    int n0 = blockIdx.x * 128, m0 = blockIdx.y * 128;
    int wm = (wid >> 2) * 64, wn = (wid & 3) * 32;

    const float* gA = X + (size_t)m0 * D_;
    const __nv_bfloat16* gB = g_Cb + (size_t)n0 * D_;
    for (int i = tid; i < 128; i += 256) cns[i] = g_norm[n0 + i];

    // per-thread load mapping: unit i -> row r0+32i, unit-in-row u (constant)
    const int r0 = tid >> 3, u = tid & 7;
    const uint32_t swz = (uint32_t)((u ^ (r0 & 7)) << 4);   // (r0+32i)&7 == r0&7
    const bool do_x2 = (blockIdx.x == 0);
    float x2 = 0.f;

    float4 pa[8];   // A prefetch: 4 units x 2 float4

    // ldg A tile kt into pa
    auto ldgA = [&](int kt) {
#pragma unroll
        for (int i = 0; i < 4; i++) {
            const float* s = gA + (size_t)(r0 + 32 * i) * D_ + kt * BK + u * 8;
            pa[2 * i]     = *reinterpret_cast<const float4*>(s);
            pa[2 * i + 1] = *reinterpret_cast<const float4*>(s + 4);
        }
    };
    // cvt + sts pa into A stage (byte offset aoff), optional x^2 accumulation
    auto stsA = [&](uint32_t aoff) {
#pragma unroll
        for (int i = 0; i < 4; i++) {
            float4 a = pa[2 * i], b = pa[2 * i + 1];
            uint4 v;
            v.x = pack_bf2(a.x, a.y);
            v.y = pack_bf2(a.z, a.w);
            v.z = pack_bf2(b.x, b.y);
            v.w = pack_bf2(b.z, b.w);
            *reinterpret_cast<uint4*>(smem + aoff + (uint32_t)(r0 + 32 * i) * 128 + swz) = v;
            if (do_x2)
                x2 += a.x * a.x + a.y * a.y + a.z * a.z + a.w * a.w
                    + b.x * b.x + b.y * b.y + b.z * b.z + b.w * b.w;
        }
    };
    auto ldB = [&](int kt, uint32_t boff) {
#pragma unroll
        for (int i = 0; i < 4; i++)
            cp16(sb + boff + (uint32_t)(r0 + 32 * i) * 128 + swz,
                 gB + (size_t)(r0 + 32 * i) * D_ + kt * BK + u * 8);
    };

    // ldmatrix row constants
    int arow[4], brow[2];
#pragma unroll
    for (int mi = 0; mi < 4; mi++)
        arow[mi] = wm + 16 * mi + (lane & 7) + 8 * ((lane >> 3) & 1);
#pragma unroll
    for (int p = 0; p < 2; p++)
        brow[p] = wn + 16 * p + (lane & 7) + 8 * ((lane >> 4) & 1);
    const int au = (lane >> 4) & 1, bu = (lane >> 3) & 1;

    float acc[4][4][4];
#pragma unroll
    for (int a = 0; a < 4; a++)
#pragma unroll
        for (int b = 0; b < 4; b++)
#pragma unroll
            for (int c = 0; c < 4; c++) acc[a][b][c] = 0.f;

    // prologue
    ldgA(0);
    stsA(SOFF_A0);
    ldgA(1);                      // prefetch A(1)
    ldB(0, SOFF_B0);
    asm volatile("cp.async.commit_group;" ::: "memory");
    ldB(1, SOFF_B0 + 16384);
    asm volatile("cp.async.commit_group;" ::: "memory");

    const int NKT = D_ / BK;      // 64
    for (int kt = 0; kt < NKT; kt++) {
        if (kt < NKT - 1) {
            asm volatile("cp.async.wait_group 1;" ::: "memory");
        } else {
            asm volatile("cp.async.wait_group 0;" ::: "memory");
        }
        __syncthreads();
        if (kt + 2 < NKT) {
            ldB(kt + 2, SOFF_B0 + (uint32_t)((kt + 2) % 3) * 16384);
            asm volatile("cp.async.commit_group;" ::: "memory");
        }

        uint32_t as = sb + ((kt & 1) ? SOFF_A1 : SOFF_A0);
        uint32_t bs = sb + SOFF_B0 + (uint32_t)(kt % 3) * 16384;

#pragma unroll
        for (int ks = 0; ks < 4; ks++) {
            uint32_t af[4][4], bf[2][4];
#pragma unroll
            for (int mi = 0; mi < 4; mi++) {
                int r = arow[mi], uu = ks * 2 + au;
                ldmx4(af[mi], as + r * 128 + ((uu ^ (r & 7)) << 4));
            }
#pragma unroll
            for (int p = 0; p < 2; p++) {
                int r = brow[p], uu = ks * 2 + bu;
                ldmx4(bf[p], bs + r * 128 + ((uu ^ (r & 7)) << 4));
            }
#pragma unroll
            for (int mi = 0; mi < 4; mi++)
#pragma unroll
                for (int p = 0; p < 2; p++) {
                    mma16816(acc[mi][2 * p],     af[mi], bf[p][0], bf[p][1]);
                    mma16816(acc[mi][2 * p + 1], af[mi], bf[p][2], bf[p][3]);
                }
        }

        if (kt + 1 < NKT) stsA((kt & 1) ? SOFF_A0 : SOFF_A1);  // A(kt+1) -> other stage
        if (kt + 2 < NKT) ldgA(kt + 2);                        // prefetch A(kt+2)
    }

    // x^2 total (bx==0 CTAs cover X exactly once)
    if (do_x2) {
        __syncthreads();          // A staging no longer needed; reuse as scratch
        float* red = (float*)smem;
#pragma unroll
        for (int off = 16; off > 0; off >>= 1)
            x2 += __shfl_xor_sync(0xffffffffu, x2, off);
        if (lane == 0) red[wid] = x2;
        __syncthreads();
        if (tid == 0) {
            float s = 0.f;
            for (int w = 0; w < 8; w++) s += red[w];
            atomicAdd(&g_xsum, (double)s);
        }
    }

    // epilogue: approx distance = ||c||^2 - 2*dot  -> g_dist
    int gid = lane >> 2, tig = lane & 3;
#pragma unroll
    for (int mi = 0; mi < 4; mi++) {
        int row = m0 + wm + 16 * mi + gid;
#pragma unroll
        for (int nj = 0; nj < 4; nj++) {
            int c = wn + 8 * nj + 2 * tig;
            float cn0 = cns[c], cn1 = cns[c + 1];
            float2 v0 = make_float2(cn0 - 2.f * acc[mi][nj][0], cn1 - 2.f * acc[mi][nj][1]);
            float2 v1 = make_float2(cn0 - 2.f * acc[mi][nj][2], cn1 - 2.f * acc[mi][nj][3]);
            *reinterpret_cast<float2*>(g_dist + (size_t)row * E_ + n0 + c) = v0;
            *reinterpret_cast<float2*>(g_dist + (size_t)(row + 8) * E_ + n0 + c) = v1;
        }
    }
}

// ---------------- argmin + candidate collection (warp per row) ---------------
__global__ __launch_bounds__(256) void k_argmin() {
    int row = (blockIdx.x * 256 + threadIdx.x) >> 5;
    int lane = threadIdx.x & 31;
    if (row >= B_) return;
    const float4* dp = reinterpret_cast<const float4*>(g_dist + (size_t)row * E_);
    float4 v[4];
    float best = INFINITY;
    int bidx = 1 << 30;
#pragma unroll
    for (int j = 0; j < 4; j++) {
        v[j] = dp[lane + 32 * j];
        int c0 = (lane + 32 * j) * 4;
        const float* f = reinterpret_cast<const float*>(&v[j]);
#pragma unroll
        for (int e = 0; e < 4; e++) {
            float d = f[e];
            int c = c0 + e;
            if (d < best || (d == best && c < bidx)) { best = d; bidx = c; }
        }
    }
#pragma unroll
    for (int off = 16; off > 0; off >>= 1) {
        float ov = __shfl_xor_sync(0xffffffffu, best, off);
        int   oi = __shfl_xor_sync(0xffffffffu, bidx, off);
        if (ov < best || (ov == best && oi < bidx)) { best = ov; bidx = oi; }
    }
    float thr = best + MARGIN;
#pragma unroll
    for (int j = 0; j < 4; j++) {
        int c0 = (lane + 32 * j) * 4;
        const float* f = reinterpret_cast<const float*>(&v[j]);
#pragma unroll
        for (int e = 0; e < 4; e++) {
            if (f[e] <= thr) {
                int p = atomicAdd(&g_ncand[row], 1);
                if (p < 8) g_cand[row][p] = c0 + e;
            }
        }
    }
    if (lane == 0) { g_idx[row] = bidx; g_rowdist[row] = best; }
}

// ---------------- exact fp32 rescore of ambiguous rows -----------------------
__global__ __launch_bounds__(128) void k_rescore(const float* __restrict__ X,
                                                 const float* __restrict__ Cb) {
    int b = blockIdx.x;
    int n = g_ncand[b];
    if (n <= 1) return;                     // unambiguous: bf16 winner stands
    __shared__ float sh[128];
    const float4* x4 = reinterpret_cast<const float4*>(X + (size_t)b * D_);
    int total = (n <= 8) ? n : E_;          // >8 candidates: full exact scan
    float bestd = INFINITY;
    int besti = 1 << 30;
    for (int c = 0; c < total; c++) {
        int e = (n <= 8) ? g_cand[b][c] : c;
        const float4* c4 = reinterpret_cast<const float4*>(Cb + (size_t)e * D_);
        float s = 0.f;
        for (int i = threadIdx.x; i < D_ / 4; i += 128) {
            float4 xv = x4[i], cv = c4[i];
            s += xv.x * cv.x + xv.y * cv.y + xv.z * cv.z + xv.w * cv.w;
        }
        sh[threadIdx.x] = s;
        __syncthreads();
        for (int st = 64; st > 0; st >>= 1) {
            if (threadIdx.x < st) sh[threadIdx.x] += sh[threadIdx.x + st];
            __syncthreads();
        }
        float d = g_norm[e] - 2.f * sh[0];
        if (d < bestd || (d == bestd && e < besti)) { bestd = d; besti = e; }
        __syncthreads();
    }
    if (threadIdx.x == 0) { g_idx[b] = besti; g_rowdist[b] = bestd; }
}

// ---------------- outputs (no X read; quantized_st == codebook row) ----------
__global__ __launch_bounds__(512) void k_out(const float* __restrict__ Cb,
                                             float* __restrict__ outQ,
                                             float* __restrict__ outEnc) {
    __shared__ float qs[D_];
    int b = blockIdx.x;
    int t = threadIdx.x;
    int idx = g_idx[b];

    if (t == 0) atomicAdd(&g_hist[idx], 1);

    // one-hot encodings: 512 floats per row = 256 float2 stores (t < 256 only)
    if (t < 256) {
        float2 e2;
        int c = 2 * t;
        e2.x = (c == idx) ? 1.f : 0.f;
        e2.y = (c + 1 == idx) ? 1.f : 0.f;
        reinterpret_cast<float2*>(outEnc + (size_t)b * E_)[t] = e2;
    }

    // stage codebook row in smem (aligned float4 reads)
    const float4* c4 = reinterpret_cast<const float4*>(Cb + (size_t)idx * D_);
    float4* q4 = reinterpret_cast<float4*>(qs);
#pragma unroll
    for (int i = 0; i < 2; i++) q4[t + 512 * i] = c4[t + 512 * i];
    __syncthreads();

    // outQ row is 4B-aligned only (global offset 1 + b*4096).
    float* o = outQ + (size_t)b * D_;
    if (t < 3) o[t] = qs[t];
    if (t == 3) o[4095] = qs[4095];
    for (int i = t; i < 1023; i += 512) {
        int j = 3 + 4 * i;
        float4 v = make_float4(qs[j], qs[j + 1], qs[j + 2], qs[j + 3]);
        *reinterpret_cast<float4*>(o + j) = v;
    }
}

// ---------------- finalize: loss from row distances + perplexity -------------
__global__ __launch_bounds__(512) void k_final(float* __restrict__ out) {
    __shared__ double sh[512];
    int t = threadIdx.x;

    // loss = 1.25 * (sum x^2 + sum_rows rowdist) / (B*D)
    double s = 0.0;
    for (int i = t; i < B_; i += 512)
        s += (double)g_rowdist[i];
    sh[t] = s;
    __syncthreads();
    for (int st = 256; st > 0; st >>= 1) {
        if (t < st) sh[t] += sh[t + st];
        __syncthreads();
    }
    double lsum = sh[0] + g_xsum;
    __syncthreads();

    double p = (double)g_hist[t] / (double)B_;
    sh[t] = p * log(p + 1e-10);
    __syncthreads();
    for (int st = 256; st > 0; st >>= 1) {
        if (t < st) sh[t] += sh[t + st];
        __syncthreads();
    }
    if (t == 0) {
        double mse = lsum / ((double)B_ * (double)D_);
        out[0] = (float)(1.25 * mse);
        out[1 + (size_t)B_ * D_] = (float)exp(-sh[0]);
    }
}

// ---------------------------------------------------------------------------
extern "C" void kernel_launch(void* const* d_in, const int* in_sizes, int n_in,
                              void* d_out, int out_size) {
    (void)in_sizes; (void)n_in; (void)out_size;
    const float* X  = (const float*)d_in[0];
    const float* Cb = (const float*)d_in[1];
    float* out = (float*)d_out;

    float* outQ   = out + 1;
    float* outEnc = out + 2 + (size_t)B_ * D_;

    cudaFuncSetAttribute(k_gemm_mma, cudaFuncAttributeMaxDynamicSharedMemorySize,
                         SMEM_GEMM);

    k_init<<<32, 256>>>();
    k_normsC<<<E_, 256>>>(Cb);
    dim3 gg(E_ / 128, B_ / 128);
    k_gemm_mma<<<gg, 256, SMEM_GEMM>>>(X);
    k_argmin<<<B_ / 8, 256>>>();
    k_rescore<<<B_, 128>>>(X, Cb);
    k_out<<<B_, 512>>>(Cb, outQ, outEnc);
    k_final<<<1, 512>>>(out);
}